// round 4
// baseline (speedup 1.0000x reference)
#include <cuda_runtime.h>
#include <math.h>

#define TT 512
#define BB 64
#define II 1024
#define HH 1024
#define NG 4096   // 4*H

// Packed fp32x2 FMA (Blackwell FFMA2): d = a*b + d elementwise on 2 packed floats.
#define FFMA2(d, a, b) asm("fma.rn.f32x2 %0, %1, %2, %0;" : "+l"(d) : "l"(a), "l"(b))
#define UNPK(lo, hi, v) asm("mov.b64 {%0, %1}, %2;" : "=f"(lo), "=f"(hi) : "l"(v))

// Scratch (allocation-free rule: __device__ globals)
__device__ __align__(16) float g_xg[(size_t)TT * BB * NG];  // x@W_ih^T + b_ih, [T,B,4H]
__device__ __align__(16) float g_c[BB * HH];                // cell state

// ---------------------------------------------------------------------------
// Input GEMM: g_xg[m, n] = sum_k x[m,k] * W_ih[n,k] + b_ih[n]
// M = 32768, N = 4096, K = 1024. 128x128 tile, KC=16, 256 thr, 8x8 micro,
// FFMA2 inner loop: A rows duplicated in smem, B natural col-pairs.
// ---------------------------------------------------------------------------
__global__ __launch_bounds__(256, 2) void xgemm_kernel(
    const float* __restrict__ A,     // x  [M, K]
    const float* __restrict__ W,     // W_ih [N, K]
    const float* __restrict__ bias)  // b_ih [N]
{
    __shared__ float sAd[16][264];   // duplicated: row r at cols 2r, 2r+1
    __shared__ float sB[16][132];

    const int K = II;
    const int bn = blockIdx.x * 128;
    const int bm = blockIdx.y * 128;
    const int tid = threadIdx.x;
    const int tx = tid & 15;       // cols tx*8 .. +7 (4 pairs)
    const int ty = tid >> 4;       // rows ty*8 .. +7

    const int lrow = tid >> 1;         // 0..127
    const int lkq  = (tid & 1) * 8;    // 0 or 8

    const float* Aptr = A + (size_t)(bm + lrow) * K + lkq;
    const float* Wptr = W + (size_t)(bn + lrow) * K + lkq;

    unsigned long long acc[8][4];      // [row][col-pair], each = 2 packed f32
#pragma unroll
    for (int i = 0; i < 8; i++)
#pragma unroll
        for (int j = 0; j < 4; j++) acc[i][j] = 0ULL;

    // prefetch chunk 0 into registers
    float4 ra0 = *(const float4*)(Aptr);
    float4 ra1 = *(const float4*)(Aptr + 4);
    float4 rb0 = *(const float4*)(Wptr);
    float4 rb1 = *(const float4*)(Wptr + 4);

#pragma unroll 1
    for (int c = 0; c < K / 16; c++) {
        __syncthreads();
        // A duplicated stores
        {
            float av[8] = {ra0.x, ra0.y, ra0.z, ra0.w, ra1.x, ra1.y, ra1.z, ra1.w};
#pragma unroll
            for (int i = 0; i < 8; i++) {
                sAd[lkq + i][2 * lrow] = av[i];
                sAd[lkq + i][2 * lrow + 1] = av[i];
            }
        }
        sB[lkq + 0][lrow] = rb0.x; sB[lkq + 1][lrow] = rb0.y;
        sB[lkq + 2][lrow] = rb0.z; sB[lkq + 3][lrow] = rb0.w;
        sB[lkq + 4][lrow] = rb1.x; sB[lkq + 5][lrow] = rb1.y;
        sB[lkq + 6][lrow] = rb1.z; sB[lkq + 7][lrow] = rb1.w;
        __syncthreads();

        if (c + 1 < K / 16) {
            int ko = (c + 1) * 16;
            ra0 = *(const float4*)(Aptr + ko);
            ra1 = *(const float4*)(Aptr + ko + 4);
            rb0 = *(const float4*)(Wptr + ko);
            rb1 = *(const float4*)(Wptr + ko + 4);
        }

#pragma unroll
        for (int kk = 0; kk < 16; kk++) {
            // 8 duplicated row-pairs (a_i, a_i)
            ulonglong2 a01 = *(const ulonglong2*)&sAd[kk][ty * 16];
            ulonglong2 a23 = *(const ulonglong2*)&sAd[kk][ty * 16 + 4];
            ulonglong2 a45 = *(const ulonglong2*)&sAd[kk][ty * 16 + 8];
            ulonglong2 a67 = *(const ulonglong2*)&sAd[kk][ty * 16 + 12];
            // 4 natural col-pairs (b_j, b_j+1)
            ulonglong2 b03 = *(const ulonglong2*)&sB[kk][tx * 8];
            ulonglong2 b47 = *(const ulonglong2*)&sB[kk][tx * 8 + 4];
            unsigned long long ad[8] = {a01.x, a01.y, a23.x, a23.y,
                                        a45.x, a45.y, a67.x, a67.y};
            unsigned long long bp[4] = {b03.x, b03.y, b47.x, b47.y};
#pragma unroll
            for (int i = 0; i < 8; i++)
#pragma unroll
                for (int j = 0; j < 4; j++) FFMA2(acc[i][j], ad[i], bp[j]);
        }
    }

    float bv[8];
#pragma unroll
    for (int j = 0; j < 8; j++) bv[j] = bias[bn + tx * 8 + j];

#pragma unroll
    for (int i = 0; i < 8; i++) {
        float v[8];
#pragma unroll
        for (int j = 0; j < 4; j++) UNPK(v[2 * j], v[2 * j + 1], acc[i][j]);
        size_t row = (size_t)(bm + ty * 8 + i);
        float* cp = g_xg + row * NG + bn + tx * 8;
        *(float4*)cp = make_float4(v[0] + bv[0], v[1] + bv[1], v[2] + bv[2], v[3] + bv[3]);
        *(float4*)(cp + 4) = make_float4(v[4] + bv[4], v[5] + bv[5], v[6] + bv[6], v[7] + bv[7]);
    }
}

// ---------------------------------------------------------------------------
// Fused LSTM step. Block j: h-columns [j*8, j*8+8) of all four gates
// (64x32 GEMM tile, K=1024) + pointwise update of its 64x8 h/c slice.
// grid=128, block=256. Thread tile 4 rows x 2 cols via FFMA2.
// ---------------------------------------------------------------------------
__device__ __forceinline__ float sigf(float x) { return 1.f / (1.f + expf(-x)); }

__global__ __launch_bounds__(256, 1) void lstm_step_kernel(
    const float* __restrict__ Hprev,  // [64, 1024]
    const float* __restrict__ Whh,    // [4096, 1024]
    const float* __restrict__ bhh,    // [4096]
    float* __restrict__ Hout,         // [64, 1024]
    int t)
{
    __shared__ float sH[2][16][68];   // [buf][kk][row]
    __shared__ float sWd[2][16][72];  // [buf][kk][2*col {dup}]
    __shared__ float sG[64][33];

    const int tid = threadIdx.x;
    const int j0 = blockIdx.x * 8;
    const int tx = tid & 15;     // col-pair: local cols 2tx, 2tx+1
    const int ty = tid >> 4;     // rows 4ty .. 4ty+3

    // loader mapping
    const int hrow = tid & 63;           // 0..63
    const int hkq  = (tid >> 6) * 4;     // 0,4,8,12
    const int wn   = tid & 31;           // local gate-col 0..31
    const int wkq2 = (tid >> 5) * 2;     // 0,2,..,14
    const int wglob = (wn >> 3) * HH + j0 + (wn & 7);   // W_hh row

    const float* Hptr = Hprev + (size_t)hrow * II + hkq;
    const float* Wptr = Whh + (size_t)wglob * II + wkq2;
    const float* xg_t = g_xg + (size_t)t * BB * NG;

    unsigned long long acc00 = 0, acc10 = 0, acc01 = 0, acc11 = 0;
    // acc{rp}{c}: rp=0 rows(4ty,4ty+1), rp=1 rows(4ty+2,4ty+3); c = local col 2tx+c

    // prologue: chunk 0 -> buffer 0
    {
        float4 hv = *(const float4*)(Hptr);
        float2 wv = *(const float2*)(Wptr);
        sH[0][hkq + 0][hrow] = hv.x; sH[0][hkq + 1][hrow] = hv.y;
        sH[0][hkq + 2][hrow] = hv.z; sH[0][hkq + 3][hrow] = hv.w;
        sWd[0][wkq2 + 0][2 * wn] = wv.x; sWd[0][wkq2 + 0][2 * wn + 1] = wv.x;
        sWd[0][wkq2 + 1][2 * wn] = wv.y; sWd[0][wkq2 + 1][2 * wn + 1] = wv.y;
    }
    __syncthreads();

    int buf = 0;
#pragma unroll 1
    for (int c = 0; c < II / 16; c++) {
        float4 nhv; float2 nwv;
        const bool more = (c + 1 < II / 16);
        if (more) {
            int ko = (c + 1) * 16;
            nhv = *(const float4*)(Hptr + ko);
            nwv = *(const float2*)(Wptr + ko);
        }

#pragma unroll
        for (int kk = 0; kk < 16; kk++) {
            ulonglong2 aa = *(const ulonglong2*)&sH[buf][kk][ty * 4];   // (r0,r1),(r2,r3)
            ulonglong2 wb = *(const ulonglong2*)&sWd[buf][kk][tx * 4];  // (w0,w0),(w1,w1)
            FFMA2(acc00, aa.x, wb.x);
            FFMA2(acc10, aa.y, wb.x);
            FFMA2(acc01, aa.x, wb.y);
            FFMA2(acc11, aa.y, wb.y);
        }

        if (more) {
            int ob = buf ^ 1;
            sH[ob][hkq + 0][hrow] = nhv.x; sH[ob][hkq + 1][hrow] = nhv.y;
            sH[ob][hkq + 2][hrow] = nhv.z; sH[ob][hkq + 3][hrow] = nhv.w;
            sWd[ob][wkq2 + 0][2 * wn] = nwv.x; sWd[ob][wkq2 + 0][2 * wn + 1] = nwv.x;
            sWd[ob][wkq2 + 1][2 * wn] = nwv.y; sWd[ob][wkq2 + 1][2 * wn + 1] = nwv.y;
            __syncthreads();
            buf = ob;
        }
    }

    // gates tile -> smem (add x-projection and recurrent bias)
    {
        float v[2][4];  // [col][row 0..3]
        UNPK(v[0][0], v[0][1], acc00); UNPK(v[0][2], v[0][3], acc10);
        UNPK(v[1][0], v[1][1], acc01); UNPK(v[1][2], v[1][3], acc11);
#pragma unroll
        for (int cc = 0; cc < 2; cc++) {
            int col = tx * 2 + cc;
            int nglob = (col >> 3) * HH + j0 + (col & 7);
            float bias2 = bhh[nglob];
#pragma unroll
            for (int rr = 0; rr < 4; rr++) {
                int row = ty * 4 + rr;
                sG[row][col] = v[cc][rr] + xg_t[(size_t)row * NG + nglob] + bias2;
            }
        }
    }
    __syncthreads();

    // pointwise update: 512 (row, hc) pairs, 2 per thread
#pragma unroll
    for (int u = 0; u < 2; u++) {
        int q = tid * 2 + u;
        int row = q >> 3;
        int hc = q & 7;
        float iv = sigf(sG[row][hc]);
        float fv = sigf(sG[row][8 + hc]);
        float gv = tanhf(sG[row][16 + hc]);
        float ov = sigf(sG[row][24 + hc]);
        int gi = row * HH + j0 + hc;
        float cv = fv * g_c[gi] + iv * gv;
        g_c[gi] = cv;
        Hout[gi] = ov * tanhf(cv);
    }
}

// ---------------------------------------------------------------------------
__global__ void initc_kernel(const float* __restrict__ c0) {
    int i = blockIdx.x * blockDim.x + threadIdx.x;
    if (i < BB * HH) g_c[i] = c0[i];
}

__global__ void finalize_kernel(const float* __restrict__ hlast,
                                float* __restrict__ outh,
                                float* __restrict__ outc) {
    int i = blockIdx.x * blockDim.x + threadIdx.x;
    if (i < BB * HH) {
        outh[i] = hlast[i];
        outc[i] = g_c[i];
    }
}

// ---------------------------------------------------------------------------
extern "C" void kernel_launch(void* const* d_in, const int* in_sizes, int n_in,
                              void* d_out, int out_size) {
    (void)n_in; (void)in_sizes;
    const float* x   = (const float*)d_in[0];  // [T, B, I]
    const float* h0  = (const float*)d_in[1];  // [B, H]
    const float* c0  = (const float*)d_in[2];  // [B, H]
    const float* Wih = (const float*)d_in[3];  // [4H, I]
    const float* Whh = (const float*)d_in[4];  // [4H, H]
    const float* bih = (const float*)d_in[5];
    const float* bhh = (const float*)d_in[6];
    float* out = (float*)d_out;

    // 1) input-side projections for all timesteps
    dim3 g1(NG / 128, (TT * BB) / 128);
    xgemm_kernel<<<g1, 256>>>(x, Wih, bih);

    // 2) cell-state init (inside the graph -> deterministic across replays)
    initc_kernel<<<(BB * HH + 255) / 256, 256>>>(c0);

    // 3) recurrence: outputs buffer doubles as the h ring
    for (int t = 0; t < TT; t++) {
        const float* hprev = (t == 0) ? h0 : out + (size_t)(t - 1) * BB * HH;
        float* hout = out + (size_t)t * BB * HH;
        lstm_step_kernel<<<HH / 8, 256>>>(hprev, Whh, bhh, hout, t);
    }

    // 4) (hT, cT) tail if the output buffer carries them
    long long need = (long long)TT * BB * HH + 2LL * BB * HH;
    if ((long long)out_size >= need) {
        const float* hlast = out + (size_t)(TT - 1) * BB * HH;
        float* outh = out + (size_t)TT * BB * HH;
        float* outc = outh + BB * HH;
        finalize_kernel<<<(BB * HH + 255) / 256, 256>>>(hlast, outh, outc);
    }
}

// round 12
// speedup vs baseline: 1.7009x; 1.7009x over previous
#include <cuda_runtime.h>
#include <cuda_bf16.h>
#include <stdint.h>
#include <math.h>

#define TT 512
#define BB 64
#define II 1024
#define HH 1024
#define NG 4096   // 4*H

// ---------------- device scratch (allocation-free rule) ----------------
__device__ __align__(16) float g_xg[(size_t)TT * BB * NG];   // x@W_ih^T + b_ih
__device__ __align__(16) float g_c[BB * HH];                 // cell state
__device__ __align__(16) __nv_bfloat16 g_xh[(size_t)TT * BB * II];
__device__ __align__(16) __nv_bfloat16 g_xl[(size_t)TT * BB * II];
__device__ __align__(16) __nv_bfloat16 g_wih_h[NG * II];
__device__ __align__(16) __nv_bfloat16 g_wih_l[NG * II];

// m16n8k16 bf16 MMA, fp32 accumulate (HMMA on sm_100a)
#define MMA16816(c, a0, a1, a2, a3, b0, b1)                                   \
    asm volatile(                                                             \
        "mma.sync.aligned.m16n8k16.row.col.f32.bf16.bf16.f32 "                \
        "{%0,%1,%2,%3}, {%4,%5,%6,%7}, {%8,%9}, {%0,%1,%2,%3};"               \
        : "+f"(c[0]), "+f"(c[1]), "+f"(c[2]), "+f"(c[3])                      \
        : "r"(a0), "r"(a1), "r"(a2), "r"(a3), "r"(b0), "r"(b1))

static __device__ __forceinline__ void store_bf16x2(__nv_bfloat16* p,
                                                    __nv_bfloat16 a,
                                                    __nv_bfloat16 b) {
    __nv_bfloat162 v; v.x = a; v.y = b;
    *(__nv_bfloat162*)p = v;
}

// ---------------------------------------------------------------------------
// Split fp32 -> bf16 (hi) + bf16 (residual lo). 4 elements/thread.
// which: 0 -> g_xh/g_xl, 1 -> g_wih_h/l
// ---------------------------------------------------------------------------
__global__ void cvt_split_kernel(const float* __restrict__ src, int which, int n) {
    int i = (blockIdx.x * blockDim.x + threadIdx.x) * 4;
    if (i >= n) return;
    __nv_bfloat16* hi = (which == 0) ? g_xh : g_wih_h;
    __nv_bfloat16* lo = (which == 0) ? g_xl : g_wih_l;
    float4 v = *(const float4*)(src + i);
    float vv[4] = {v.x, v.y, v.z, v.w};
    __nv_bfloat16 h4[4], l4[4];
#pragma unroll
    for (int k = 0; k < 4; k++) {
        h4[k] = __float2bfloat16(vv[k]);
        l4[k] = __float2bfloat16(vv[k] - __bfloat162float(h4[k]));
    }
    store_bf16x2(hi + i, h4[0], h4[1]);
    store_bf16x2(hi + i + 2, h4[2], h4[3]);
    store_bf16x2(lo + i, l4[0], l4[1]);
    store_bf16x2(lo + i + 2, l4[2], l4[3]);
}

// ---------------------------------------------------------------------------
// Input GEMM on tensor cores, 3-term split-bf16.
// g_xg[m,n] = sum_k x[m,k]*W_ih[n,k] + b_ih[n].  M=32768, N=4096, K=1024.
// Block 128x64, 8 warps (warp tile m64 x n16), K-chunk 32.
// smem stride 40 bf16 (80B) -> conflict-free fragment loads.
// ---------------------------------------------------------------------------
#define SA 40
__global__ __launch_bounds__(256, 1) void xgemm_tc(const float* __restrict__ bias) {
    __shared__ __nv_bfloat16 sAh[128 * SA];
    __shared__ __nv_bfloat16 sAl[128 * SA];
    __shared__ __nv_bfloat16 sBh[64 * SA];
    __shared__ __nv_bfloat16 sBl[64 * SA];

    const int tid = threadIdx.x, lane = tid & 31, warp = tid >> 5;
    const int bm = blockIdx.y * 128, bn = blockIdx.x * 64;
    const int wm = (warp >> 2) * 64, wn = (warp & 3) * 16;

    const int ar = tid >> 3, akq = tid & 7;   // staging: rows ar+32i, 4 bf16 @ k=akq*4
    const __nv_bfloat16* gAh = g_xh + (size_t)(bm + ar) * II + akq * 4;
    const __nv_bfloat16* gAl = g_xl + (size_t)(bm + ar) * II + akq * 4;
    const __nv_bfloat16* gBh = g_wih_h + (size_t)(bn + ar) * II + akq * 4;
    const __nv_bfloat16* gBl = g_wih_l + (size_t)(bn + ar) * II + akq * 4;

    float acc[4][2][4];
#pragma unroll
    for (int mi = 0; mi < 4; mi++)
#pragma unroll
        for (int ni = 0; ni < 2; ni++)
#pragma unroll
            for (int r = 0; r < 4; r++) acc[mi][ni][r] = 0.f;

    uint2 pah[4], pal[4], pbh[2], pbl[2];
#pragma unroll
    for (int i = 0; i < 4; i++) {
        pah[i] = *(const uint2*)(gAh + (size_t)i * 32 * II);
        pal[i] = *(const uint2*)(gAl + (size_t)i * 32 * II);
    }
#pragma unroll
    for (int i = 0; i < 2; i++) {
        pbh[i] = *(const uint2*)(gBh + (size_t)i * 32 * II);
        pbl[i] = *(const uint2*)(gBl + (size_t)i * 32 * II);
    }

#pragma unroll 1
    for (int c = 0; c < II / 32; c++) {
#pragma unroll
        for (int i = 0; i < 4; i++) {
            *(uint2*)&sAh[(ar + i * 32) * SA + akq * 4] = pah[i];
            *(uint2*)&sAl[(ar + i * 32) * SA + akq * 4] = pal[i];
        }
#pragma unroll
        for (int i = 0; i < 2; i++) {
            *(uint2*)&sBh[(ar + i * 32) * SA + akq * 4] = pbh[i];
            *(uint2*)&sBl[(ar + i * 32) * SA + akq * 4] = pbl[i];
        }
        __syncthreads();

        if (c + 1 < II / 32) {
            int ko = (c + 1) * 32;
#pragma unroll
            for (int i = 0; i < 4; i++) {
                pah[i] = *(const uint2*)(gAh + (size_t)i * 32 * II + ko);
                pal[i] = *(const uint2*)(gAl + (size_t)i * 32 * II + ko);
            }
#pragma unroll
            for (int i = 0; i < 2; i++) {
                pbh[i] = *(const uint2*)(gBh + (size_t)i * 32 * II + ko);
                pbl[i] = *(const uint2*)(gBl + (size_t)i * 32 * II + ko);
            }
        }

#pragma unroll
        for (int ks = 0; ks < 32; ks += 16) {
            uint32_t bh[2][2], bl[2][2];
#pragma unroll
            for (int ni = 0; ni < 2; ni++) {
                int nr = wn + ni * 8 + (lane >> 2);
                int kb = ks + (lane & 3) * 2;
                bh[ni][0] = *(const uint32_t*)&sBh[nr * SA + kb];
                bh[ni][1] = *(const uint32_t*)&sBh[nr * SA + kb + 8];
                bl[ni][0] = *(const uint32_t*)&sBl[nr * SA + kb];
                bl[ni][1] = *(const uint32_t*)&sBl[nr * SA + kb + 8];
            }
#pragma unroll
            for (int mi = 0; mi < 4; mi++) {
                int r0 = wm + mi * 16 + (lane >> 2);
                int ka = ks + (lane & 3) * 2;
                uint32_t ah0 = *(const uint32_t*)&sAh[r0 * SA + ka];
                uint32_t ah1 = *(const uint32_t*)&sAh[(r0 + 8) * SA + ka];
                uint32_t ah2 = *(const uint32_t*)&sAh[r0 * SA + ka + 8];
                uint32_t ah3 = *(const uint32_t*)&sAh[(r0 + 8) * SA + ka + 8];
                uint32_t al0 = *(const uint32_t*)&sAl[r0 * SA + ka];
                uint32_t al1 = *(const uint32_t*)&sAl[(r0 + 8) * SA + ka];
                uint32_t al2 = *(const uint32_t*)&sAl[r0 * SA + ka + 8];
                uint32_t al3 = *(const uint32_t*)&sAl[(r0 + 8) * SA + ka + 8];
#pragma unroll
                for (int ni = 0; ni < 2; ni++) {
                    MMA16816(acc[mi][ni], ah0, ah1, ah2, ah3, bh[ni][0], bh[ni][1]);
                    MMA16816(acc[mi][ni], ah0, ah1, ah2, ah3, bl[ni][0], bl[ni][1]);
                    MMA16816(acc[mi][ni], al0, al1, al2, al3, bh[ni][0], bh[ni][1]);
                }
            }
        }
        __syncthreads();
    }

#pragma unroll
    for (int mi = 0; mi < 4; mi++) {
        int r0 = bm + wm + mi * 16 + (lane >> 2);
#pragma unroll
        for (int ni = 0; ni < 2; ni++) {
            int cc = bn + wn + ni * 8 + (lane & 3) * 2;
            float b0 = bias[cc], b1 = bias[cc + 1];
            float2 v0 = make_float2(acc[mi][ni][0] + b0, acc[mi][ni][1] + b1);
            float2 v1 = make_float2(acc[mi][ni][2] + b0, acc[mi][ni][3] + b1);
            *(float2*)&g_xg[(size_t)r0 * NG + cc] = v0;
            *(float2*)&g_xg[(size_t)(r0 + 8) * NG + cc] = v1;
        }
    }
}

// ---------------------------------------------------------------------------
// Fused LSTM step (PROVEN fp32 path from Round 3, unchanged).
// Block j handles h-columns [j*8, j*8+8) of ALL FOUR gates.
// grid=128, block=128.
// ---------------------------------------------------------------------------
__device__ __forceinline__ float sigf(float x) { return 1.f / (1.f + expf(-x)); }

__global__ __launch_bounds__(128, 1) void lstm_step_kernel(
    const float* __restrict__ Hprev,  // [64, 1024]
    const float* __restrict__ Whh,    // [4096, 1024]
    const float* __restrict__ bhh,    // [4096]
    float* __restrict__ Hout,         // [64, 1024]
    int t)
{
    __shared__ float sH[2][16][68];
    __shared__ float sW[2][16][36];
    __shared__ float sG[64][33];

    const int tid = threadIdx.x;
    const int j0 = blockIdx.x * 8;
    const int tx = tid & 15;     // cols tx*2, tx*2+1 (local 0..31)
    const int ty = tid >> 4;     // rows ty*8 .. ty*8+7

    const int hrow = tid >> 1;           // 0..63
    const int hkq  = (tid & 1) * 8;      // 0 or 8
    const int wn   = tid >> 2;           // 0..31 local gate-col
    const int wkq  = (tid & 3) * 4;      // 0,4,8,12
    const int wglob = (wn >> 3) * HH + j0 + (wn & 7);   // W_hh row

    const float* Hptr = Hprev + (size_t)hrow * II + hkq;
    const float* Wptr = Whh + (size_t)wglob * II + wkq;
    const float* xg_t = g_xg + (size_t)t * BB * NG;

    float acc[8][2];
#pragma unroll
    for (int r = 0; r < 8; r++) { acc[r][0] = 0.f; acc[r][1] = 0.f; }

    {
        float4 ha = *(const float4*)(Hptr);
        float4 hb = *(const float4*)(Hptr + 4);
        float4 wv = *(const float4*)(Wptr);
        sH[0][hkq + 0][hrow] = ha.x; sH[0][hkq + 1][hrow] = ha.y;
        sH[0][hkq + 2][hrow] = ha.z; sH[0][hkq + 3][hrow] = ha.w;
        sH[0][hkq + 4][hrow] = hb.x; sH[0][hkq + 5][hrow] = hb.y;
        sH[0][hkq + 6][hrow] = hb.z; sH[0][hkq + 7][hrow] = hb.w;
        sW[0][wkq + 0][wn] = wv.x; sW[0][wkq + 1][wn] = wv.y;
        sW[0][wkq + 2][wn] = wv.z; sW[0][wkq + 3][wn] = wv.w;
    }
    __syncthreads();

    int buf = 0;
#pragma unroll 1
    for (int c = 0; c < II / 16; c++) {
        float4 nha, nhb, nwv;
        const bool more = (c + 1 < II / 16);
        if (more) {
            int ko = (c + 1) * 16;
            nha = *(const float4*)(Hptr + ko);
            nhb = *(const float4*)(Hptr + ko + 4);
            nwv = *(const float4*)(Wptr + ko);
        }

#pragma unroll
        for (int kk = 0; kk < 16; kk++) {
            float4 a0 = *(const float4*)&sH[buf][kk][ty * 8];
            float4 a1 = *(const float4*)&sH[buf][kk][ty * 8 + 4];
            float2 bb = *(const float2*)&sW[buf][kk][tx * 2];
            float av[8] = {a0.x, a0.y, a0.z, a0.w, a1.x, a1.y, a1.z, a1.w};
#pragma unroll
            for (int r = 0; r < 8; r++) {
                acc[r][0] += av[r] * bb.x;
                acc[r][1] += av[r] * bb.y;
            }
        }

        if (more) {
            int ob = buf ^ 1;
            sH[ob][hkq + 0][hrow] = nha.x; sH[ob][hkq + 1][hrow] = nha.y;
            sH[ob][hkq + 2][hrow] = nha.z; sH[ob][hkq + 3][hrow] = nha.w;
            sH[ob][hkq + 4][hrow] = nhb.x; sH[ob][hkq + 5][hrow] = nhb.y;
            sH[ob][hkq + 6][hrow] = nhb.z; sH[ob][hkq + 7][hrow] = nhb.w;
            sW[ob][wkq + 0][wn] = nwv.x; sW[ob][wkq + 1][wn] = nwv.y;
            sW[ob][wkq + 2][wn] = nwv.z; sW[ob][wkq + 3][wn] = nwv.w;
            __syncthreads();
            buf = ob;
        }
    }

#pragma unroll
    for (int r = 0; r < 8; r++) {
#pragma unroll
        for (int cc = 0; cc < 2; cc++) {
            int row = ty * 8 + r;
            int col = tx * 2 + cc;
            int nglob = (col >> 3) * HH + j0 + (col & 7);
            sG[row][col] = acc[r][cc] + xg_t[(size_t)row * NG + nglob] + bhh[nglob];
        }
    }
    __syncthreads();

#pragma unroll
    for (int u = 0; u < 4; u++) {
        int q = tid * 4 + u;
        int row = q >> 3;
        int hc = q & 7;
        float iv = sigf(sG[row][hc]);
        float fv = sigf(sG[row][8 + hc]);
        float gv = tanhf(sG[row][16 + hc]);
        float ov = sigf(sG[row][24 + hc]);
        int gi = row * HH + j0 + hc;
        float cv = fv * g_c[gi] + iv * gv;
        g_c[gi] = cv;
        Hout[gi] = ov * tanhf(cv);
    }
}

// ---------------------------------------------------------------------------
__global__ void initc_kernel(const float* __restrict__ c0) {
    int i = blockIdx.x * blockDim.x + threadIdx.x;
    if (i < BB * HH) g_c[i] = c0[i];
}

__global__ void finalize_kernel(const float* __restrict__ hlast,
                                float* __restrict__ outh,
                                float* __restrict__ outc) {
    int i = blockIdx.x * blockDim.x + threadIdx.x;
    if (i < BB * HH) {
        outh[i] = hlast[i];
        outc[i] = g_c[i];
    }
}

// ---------------------------------------------------------------------------
extern "C" void kernel_launch(void* const* d_in, const int* in_sizes, int n_in,
                              void* d_out, int out_size) {
    (void)n_in; (void)in_sizes;
    const float* x   = (const float*)d_in[0];  // [T, B, I]
    const float* h0  = (const float*)d_in[1];  // [B, H]
    const float* c0  = (const float*)d_in[2];  // [B, H]
    const float* Wih = (const float*)d_in[3];  // [4H, I]
    const float* Whh = (const float*)d_in[4];  // [4H, H]
    const float* bih = (const float*)d_in[5];
    const float* bhh = (const float*)d_in[6];
    float* out = (float*)d_out;

    // 1) split conversions for tensor-core input GEMM
    {
        int n1 = TT * BB * II;
        cvt_split_kernel<<<n1 / 1024, 256>>>(x, 0, n1);
        int n2 = NG * II;
        cvt_split_kernel<<<n2 / 1024, 256>>>(Wih, 1, n2);
    }

    // 2) cell-state init (inside the graph -> deterministic across replays)
    initc_kernel<<<(BB * HH + 255) / 256, 256>>>(c0);

    // 3) input projections for all timesteps (tensor cores)
    {
        dim3 g(NG / 64, (TT * BB) / 128);
        xgemm_tc<<<g, 256>>>(bih);
    }

    // 4) recurrence (proven fp32 path): outputs buffer doubles as the h ring
    for (int t = 0; t < TT; t++) {
        const float* hprev = (t == 0) ? h0 : out + (size_t)(t - 1) * BB * HH;
        float* hout = out + (size_t)t * BB * HH;
        lstm_step_kernel<<<HH / 8, 128>>>(hprev, Whh, bhh, hout, t);
    }

    // 5) (hT, cT) tail if the output buffer carries them
    long long need = (long long)TT * BB * HH + 2LL * BB * HH;
    if ((long long)out_size >= need) {
        const float* hlast = out + (size_t)(TT - 1) * BB * HH;
        float* outh = out + (size_t)TT * BB * HH;
        float* outc = outh + BB * HH;
        finalize_kernel<<<(BB * HH + 255) / 256, 256>>>(hlast, outh, outc);
    }
}